// round 14
// baseline (speedup 1.0000x reference)
#include <cuda_runtime.h>

#define NUM_NODES 50000
#define C 64
#define NUM_EDGES 800000
#define HALF_E (NUM_EDGES / 2)
#define OCT_E (NUM_EDGES / 8)

// Scratch (allocation-free rule: __device__ globals)
// One extra trash row: invalid edges RED into it harmlessly.
__device__ __align__(16) float g_aggr[(NUM_NODES + 1) * C];
__device__ float g_deg[NUM_NODES];
__device__ __align__(16) float g_Wt[128 * 64];    // W transposed: [k][o]
__device__ __align__(16) int2 g_edges[NUM_EDGES]; // {row*256, col*256} byte offsets

// ---------------------------------------------------------------------------
// s2 Kernel: transpose W [o][k] -> g_Wt [k][o]. 32 blocks x 256.
// ---------------------------------------------------------------------------
__global__ void wprep_kernel(const float* __restrict__ W) {
    int i = blockIdx.x * 256 + threadIdx.x;
    if (i < 64 * 128) {
        int o = i >> 7;
        int k = i & 127;
        g_Wt[k * 64 + o] = W[i];
    }
}

// ---------------------------------------------------------------------------
// Kernel: PACK (vectorized, 2 edges/thread). Per-block dtype detect via
// int64 view of the row half (in-bounds for both widths). Grid 625 x 640.
// ---------------------------------------------------------------------------
__global__ void pack_kernel(const void* __restrict__ ei_raw) {
    int t = blockIdx.x * 640 + threadIdx.x;   // [0, HALF_E)

    const long long* ei64 = (const long long*)ei_raw;
    longlong2 rv = __ldg((const longlong2*)ei64 + t);   // edges 2t, 2t+1 row half
    bool in0 = (rv.x >= 0 && rv.x < NUM_NODES);
    bool in1 = (rv.y >= 0 && rv.y < NUM_NODES);
    int is64 = __syncthreads_and(in0 && in1);

    long long r0, r1, c0, c1;
    if (is64) {
        r0 = rv.x; r1 = rv.y;
        longlong2 cv = __ldg((const longlong2*)(ei64 + NUM_EDGES) + t);
        c0 = cv.x; c1 = cv.y;
    } else {
        const int* ei = (const int*)ei_raw;
        int2 rv32 = __ldg((const int2*)ei + t);
        r0 = rv32.x; r1 = rv32.y;
        int2 cv32 = __ldg((const int2*)(ei + NUM_EDGES) + t);
        c0 = cv32.x; c1 = cv32.y;
    }
    bool ok0 = (r0 >= 0 && r0 < NUM_NODES && c0 >= 0 && c0 < NUM_NODES);
    bool ok1 = (r1 >= 0 && r1 < NUM_NODES && c1 >= 0 && c1 < NUM_NODES);

    int4 pk;
    pk.x = ok0 ? (int)r0 * 256 : 0;
    pk.y = ok0 ? (int)c0 * 256 : NUM_NODES * 256;
    pk.z = ok1 ? (int)r1 * 256 : 0;
    pk.w = ok1 ? (int)c1 * 256 : NUM_NODES * 256;
    ((int4*)g_edges)[t] = pk;

    if (ok0) atomicAdd(&g_deg[(int)c0], 1.0f);
    if (ok1) atomicAdd(&g_deg[(int)c1], 1.0f);
}

// ---------------------------------------------------------------------------
// Kernel: OCTET slim scatter — 16 lanes per 8-edge group. Four broadcast
// int4 loads (8 edges' offsets), then 8 independent LDG.128 + 8 RED.128
// -> MLP=8. Branch-free; 16 lanes per 256B row preserved.
// Grid exact: OCT_E * 16 / 256 = 6250.
// ---------------------------------------------------------------------------
__global__ void scatter_kernel(const float* __restrict__ x) {
    int idx = blockIdx.x * 256 + threadIdx.x;
    int q     = idx >> 4;        // octet index [0, OCT_E)
    int chunk = idx & 15;

    const int4* eq = (const int4*)g_edges;
    int4 o01 = __ldg(eq + 4 * q);
    int4 o23 = __ldg(eq + 4 * q + 1);
    int4 o45 = __ldg(eq + 4 * q + 2);
    int4 o67 = __ldg(eq + 4 * q + 3);

    float4 v0 = __ldg((const float4*)((const char*)x + o01.x) + chunk);
    float4 v1 = __ldg((const float4*)((const char*)x + o01.z) + chunk);
    float4 v2 = __ldg((const float4*)((const char*)x + o23.x) + chunk);
    float4 v3 = __ldg((const float4*)((const char*)x + o23.z) + chunk);
    float4 v4 = __ldg((const float4*)((const char*)x + o45.x) + chunk);
    float4 v5 = __ldg((const float4*)((const char*)x + o45.z) + chunk);
    float4 v6 = __ldg((const float4*)((const char*)x + o67.x) + chunk);
    float4 v7 = __ldg((const float4*)((const char*)x + o67.z) + chunk);

    int cb = chunk << 2;
    float* d0 = (float*)((char*)g_aggr + o01.y) + cb;
    float* d1 = (float*)((char*)g_aggr + o01.w) + cb;
    float* d2 = (float*)((char*)g_aggr + o23.y) + cb;
    float* d3 = (float*)((char*)g_aggr + o23.w) + cb;
    float* d4 = (float*)((char*)g_aggr + o45.y) + cb;
    float* d5 = (float*)((char*)g_aggr + o45.w) + cb;
    float* d6 = (float*)((char*)g_aggr + o67.y) + cb;
    float* d7 = (float*)((char*)g_aggr + o67.w) + cb;
    asm volatile("red.global.add.v4.f32 [%0], {%1,%2,%3,%4};"
                 :: "l"(d0), "f"(v0.x), "f"(v0.y), "f"(v0.z), "f"(v0.w) : "memory");
    asm volatile("red.global.add.v4.f32 [%0], {%1,%2,%3,%4};"
                 :: "l"(d1), "f"(v1.x), "f"(v1.y), "f"(v1.z), "f"(v1.w) : "memory");
    asm volatile("red.global.add.v4.f32 [%0], {%1,%2,%3,%4};"
                 :: "l"(d2), "f"(v2.x), "f"(v2.y), "f"(v2.z), "f"(v2.w) : "memory");
    asm volatile("red.global.add.v4.f32 [%0], {%1,%2,%3,%4};"
                 :: "l"(d3), "f"(v3.x), "f"(v3.y), "f"(v3.z), "f"(v3.w) : "memory");
    asm volatile("red.global.add.v4.f32 [%0], {%1,%2,%3,%4};"
                 :: "l"(d4), "f"(v4.x), "f"(v4.y), "f"(v4.z), "f"(v4.w) : "memory");
    asm volatile("red.global.add.v4.f32 [%0], {%1,%2,%3,%4};"
                 :: "l"(d5), "f"(v5.x), "f"(v5.y), "f"(v5.z), "f"(v5.w) : "memory");
    asm volatile("red.global.add.v4.f32 [%0], {%1,%2,%3,%4};"
                 :: "l"(d6), "f"(v6.x), "f"(v6.y), "f"(v6.z), "f"(v6.w) : "memory");
    asm volatile("red.global.add.v4.f32 [%0], {%1,%2,%3,%4};"
                 :: "l"(d7), "f"(v7.x), "f"(v7.y), "f"(v7.z), "f"(v7.w) : "memory");
}

// ---------------------------------------------------------------------------
// s2 Kernel: x_gemm — out[n] = x[n] @ W1^T + b   (K = 64, W1 = W[:, :64])
// ---------------------------------------------------------------------------
#define XF_STRIDE 65
#define XG_SMEM ((64 * 64 + 64 * XF_STRIDE) * 4)

__global__ void __launch_bounds__(256)
x_gemm_kernel(const float* __restrict__ x,
              const float* __restrict__ b,
              float* __restrict__ out) {
    extern __shared__ float sm[];
    float* Wt = sm;                 // [k][o] k=0..63, stride 64
    float* F  = sm + 64 * 64;       // [c][n] stride 65

    int t = threadIdx.x;
    int base = blockIdx.x * 64;

    #pragma unroll
    for (int i = t; i < 64 * 64 / 4; i += 256)
        ((float4*)Wt)[i] = ((const float4*)g_Wt)[i];     // rows 0..63

    #pragma unroll
    for (int i = t; i < 64 * 64; i += 256) {
        int nl = i >> 6;
        int c  = i & 63;
        int n  = base + nl;
        F[c * XF_STRIDE + nl] = (n < NUM_NODES) ? x[n * C + c] : 0.f;
    }
    __syncthreads();

    int nl = t & 63;
    int o0 = (t >> 6) << 4;   // 0,16,32,48 (warp-uniform)
    int n  = base + nl;

    unsigned long long acc[8];
    #pragma unroll
    for (int p = 0; p < 8; p++) acc[p] = 0ULL;

    const float* frow = F + nl;
    const float* wrow = Wt + o0;

    #pragma unroll 8
    for (int k = 0; k < 64; k++) {
        float f = frow[k * XF_STRIDE];
        unsigned long long fp;
        asm("mov.b64 %0, {%1, %1};" : "=l"(fp) : "f"(f));
        const ulonglong2* wv = (const ulonglong2*)(wrow + k * 64);
        ulonglong2 w01 = wv[0];
        ulonglong2 w23 = wv[1];
        ulonglong2 w45 = wv[2];
        ulonglong2 w67 = wv[3];
        asm("fma.rn.f32x2 %0, %1, %2, %0;" : "+l"(acc[0]) : "l"(w01.x), "l"(fp));
        asm("fma.rn.f32x2 %0, %1, %2, %0;" : "+l"(acc[1]) : "l"(w01.y), "l"(fp));
        asm("fma.rn.f32x2 %0, %1, %2, %0;" : "+l"(acc[2]) : "l"(w23.x), "l"(fp));
        asm("fma.rn.f32x2 %0, %1, %2, %0;" : "+l"(acc[3]) : "l"(w23.y), "l"(fp));
        asm("fma.rn.f32x2 %0, %1, %2, %0;" : "+l"(acc[4]) : "l"(w45.x), "l"(fp));
        asm("fma.rn.f32x2 %0, %1, %2, %0;" : "+l"(acc[5]) : "l"(w45.y), "l"(fp));
        asm("fma.rn.f32x2 %0, %1, %2, %0;" : "+l"(acc[6]) : "l"(w67.x), "l"(fp));
        asm("fma.rn.f32x2 %0, %1, %2, %0;" : "+l"(acc[7]) : "l"(w67.y), "l"(fp));
    }

    if (n >= NUM_NODES) return;

    float* orow = out + n * C + o0;
    #pragma unroll
    for (int j = 0; j < 4; j++) {
        float lo0, hi0, lo1, hi1;
        asm("mov.b64 {%0, %1}, %2;" : "=f"(lo0), "=f"(hi0) : "l"(acc[2 * j]));
        asm("mov.b64 {%0, %1}, %2;" : "=f"(lo1), "=f"(hi1) : "l"(acc[2 * j + 1]));
        float4 r;
        r.x = lo0 + b[o0 + 4 * j + 0];
        r.y = hi0 + b[o0 + 4 * j + 1];
        r.z = lo1 + b[o0 + 4 * j + 2];
        r.w = hi1 + b[o0 + 4 * j + 3];
        *(float4*)(orow + 4 * j) = r;
    }
}

// ---------------------------------------------------------------------------
// Kernel: aggr_gemm — out[n] += (aggr[n]*rdeg) @ W2^T   (K = 64, W2 = W[:, 64:])
// ---------------------------------------------------------------------------
#define AG_SMEM ((64 * 64 + 64 * XF_STRIDE + 64) * 4)

__global__ void __launch_bounds__(256)
aggr_gemm_kernel(float* __restrict__ out) {
    extern __shared__ float sm[];
    float* Wt   = sm;                          // [k][o] k=64..127
    float* F    = sm + 64 * 64;                // [c][n] stride 65
    float* rdeg = sm + 64 * 64 + 64 * XF_STRIDE;

    int t = threadIdx.x;
    int base = blockIdx.x * 64;

    #pragma unroll
    for (int i = t; i < 64 * 64 / 4; i += 256)
        ((float4*)Wt)[i] = ((const float4*)(g_Wt + 64 * 64))[i];  // rows 64..127

    if (t < 64) {
        int n = base + t;
        rdeg[t] = (n < NUM_NODES) ? __frcp_rn(fmaxf(g_deg[n], 1.0f)) : 0.0f;
    }
    __syncthreads();

    #pragma unroll
    for (int i = t; i < 64 * 64; i += 256) {
        int nl = i >> 6;
        int c  = i & 63;
        int n  = base + nl;
        F[c * XF_STRIDE + nl] = (n < NUM_NODES) ? g_aggr[n * C + c] * rdeg[nl] : 0.f;
    }
    __syncthreads();

    int nl = t & 63;
    int o0 = (t >> 6) << 4;
    int n  = base + nl;

    unsigned long long acc[8];
    #pragma unroll
    for (int p = 0; p < 8; p++) acc[p] = 0ULL;

    const float* frow = F + nl;
    const float* wrow = Wt + o0;

    #pragma unroll 8
    for (int k = 0; k < 64; k++) {
        float f = frow[k * XF_STRIDE];
        unsigned long long fp;
        asm("mov.b64 %0, {%1, %1};" : "=l"(fp) : "f"(f));
        const ulonglong2* wv = (const ulonglong2*)(wrow + k * 64);
        ulonglong2 w01 = wv[0];
        ulonglong2 w23 = wv[1];
        ulonglong2 w45 = wv[2];
        ulonglong2 w67 = wv[3];
        asm("fma.rn.f32x2 %0, %1, %2, %0;" : "+l"(acc[0]) : "l"(w01.x), "l"(fp));
        asm("fma.rn.f32x2 %0, %1, %2, %0;" : "+l"(acc[1]) : "l"(w01.y), "l"(fp));
        asm("fma.rn.f32x2 %0, %1, %2, %0;" : "+l"(acc[2]) : "l"(w23.x), "l"(fp));
        asm("fma.rn.f32x2 %0, %1, %2, %0;" : "+l"(acc[3]) : "l"(w23.y), "l"(fp));
        asm("fma.rn.f32x2 %0, %1, %2, %0;" : "+l"(acc[4]) : "l"(w45.x), "l"(fp));
        asm("fma.rn.f32x2 %0, %1, %2, %0;" : "+l"(acc[5]) : "l"(w45.y), "l"(fp));
        asm("fma.rn.f32x2 %0, %1, %2, %0;" : "+l"(acc[6]) : "l"(w67.x), "l"(fp));
        asm("fma.rn.f32x2 %0, %1, %2, %0;" : "+l"(acc[7]) : "l"(w67.y), "l"(fp));
    }

    if (n >= NUM_NODES) return;

    float* orow = out + n * C + o0;
    #pragma unroll
    for (int j = 0; j < 4; j++) {
        float lo0, hi0, lo1, hi1;
        asm("mov.b64 {%0, %1}, %2;" : "=f"(lo0), "=f"(hi0) : "l"(acc[2 * j]));
        asm("mov.b64 {%0, %1}, %2;" : "=f"(lo1), "=f"(hi1) : "l"(acc[2 * j + 1]));
        float4 r = *(float4*)(orow + 4 * j);
        r.x += lo0; r.y += hi0; r.z += lo1; r.w += hi1;
        *(float4*)(orow + 4 * j) = r;
    }
}

// ---------------------------------------------------------------------------
extern "C" void kernel_launch(void* const* d_in, const int* in_sizes, int n_in,
                              void* d_out, int out_size) {
    const float* x   = (const float*)d_in[0];
    const void*  ei  = d_in[1];
    const float* W   = (const float*)d_in[2];
    const float* b   = (const float*)d_in[3];
    float*       out = (float*)d_out;

    // Host-side resources created once (no device allocation involved).
    static cudaStream_t s2 = nullptr;
    static cudaEvent_t ev_fork = nullptr, ev_aggr = nullptr, ev_join = nullptr;
    if (s2 == nullptr) {
        cudaStreamCreateWithFlags(&s2, cudaStreamNonBlocking);
        cudaEventCreateWithFlags(&ev_fork, cudaEventDisableTiming);
        cudaEventCreateWithFlags(&ev_aggr, cudaEventDisableTiming);
        cudaEventCreateWithFlags(&ev_join, cudaEventDisableTiming);
    }

    void* aggr_ptr = nullptr;
    void* deg_ptr  = nullptr;
    cudaGetSymbolAddress(&aggr_ptr, g_aggr);
    cudaGetSymbolAddress(&deg_ptr, g_deg);

    // Main: memset(deg) -> pack   (pack needs deg zeroed)
    cudaMemsetAsync(deg_ptr, 0, NUM_NODES * sizeof(float));

    // Fork s2: memset(aggr) -> wprep -> x_gemm, concurrent with pack.
    cudaEventRecord(ev_fork, 0);
    cudaStreamWaitEvent(s2, ev_fork, 0);
    cudaMemsetAsync(aggr_ptr, 0, NUM_NODES * C * sizeof(float), s2);
    cudaEventRecord(ev_aggr, s2);
    wprep_kernel<<<32, 256, 0, s2>>>(W);
    x_gemm_kernel<<<(NUM_NODES + 63) / 64, 256, XG_SMEM, s2>>>(x, b, out);
    cudaEventRecord(ev_join, s2);

    pack_kernel<<<HALF_E / 640, 640>>>(ei);

    // Scatter needs aggr zeroed (s2) + pack (main).
    cudaStreamWaitEvent(0, ev_aggr, 0);
    scatter_kernel<<<(OCT_E * 16) / 256, 256>>>(x);

    // Join: aggr_gemm needs scatter (main) + wprep/x_gemm (s2).
    cudaStreamWaitEvent(0, ev_join, 0);
    aggr_gemm_kernel<<<(NUM_NODES + 63) / 64, 256, AG_SMEM>>>(out);
}